// round 16
// baseline (speedup 1.0000x reference)
#include <cuda_runtime.h>

#define BATCH  4
#define NPTS   8192
#define TOTAL  (BATCH * NPTS)
#define NB     1024
#define XMIN   (-5.0f)
#define BH     (10.0f / (float)NB)
#define INVH   ((float)NB / 10.0f)

#define QB    256            // queries per tile
#define CWIN  1280           // full certification window
#define QWIN  (CWIN / 4)     // 320 candidates per nn subunit
#define GRID  148            // persistent blocks (1 per SM, co-resident)

#define SCALE (1.0f / (float)TOTAL)

// Scratch (__device__ globals — no allocation allowed):
__device__ float4   g_sorted[2][TOTAL];       // (x,y,z,|p|^2), bucket-sorted by x
__device__ int      g_seghist[8][8][NB];      // per-(ab, segment) bucket counts
__device__ int      g_segbase[8][8][NB];
__device__ int      g_off[2][BATCH][NB + 1];
__device__ unsigned g_bestbits[2][TOTAL];     // merged window min (float bits, >=0)
__device__ int      g_nfail;
__device__ int      g_fail[2 * TOTAL];
__device__ unsigned g_bcnt[8];                // barrier counters (self-reset)
__device__ unsigned g_bgen[8];                // barrier generations (monotone)

__device__ __forceinline__ int bucket_of(float x) {
    int b = (int)floorf((x - XMIN) * INVH);
    return min(max(b, 0), NB - 1);
}

// Device-wide barrier: all GRID blocks co-resident (1 block/SM).
__device__ __forceinline__ void gbar(int i) {
    __syncthreads();
    if (threadIdx.x == 0) {
        volatile unsigned* genp = &g_bgen[i];
        unsigned g = *genp;
        __threadfence();
        if (atomicAdd(&g_bcnt[i], 1u) == GRID - 1u) {
            g_bcnt[i] = 0u;          // reset for next graph replay
            __threadfence();
            atomicAdd(&g_bgen[i], 1u);
        } else {
            while (*genp == g) __nanosleep(64);
        }
    }
    __syncthreads();
}

__global__ __launch_bounds__(1024, 1) void mega_kernel(const float* __restrict__ p1,
                                                       const float* __restrict__ p2,
                                                       float* __restrict__ out) {
    __shared__ float4 smem4[8 * QWIN];        // 40 KB, re-aliased per phase
    int* sint = (int*)smem4;

    const int tid = threadIdx.x;
    const int bid = blockIdx.x;

    // ---------- P0: per-segment histogram (64 segments = 8 ab x 8 seg) ----------
    if (bid < 64) {
        const int ab = bid >> 3, sg = bid & 7;
        const int a = ab >> 2, b = ab & 3;
        const float* __restrict__ src = (a ? p2 : p1) + (b * NPTS + sg * 1024) * 3;
        sint[tid] = 0;
        __syncthreads();
        atomicAdd(&sint[bucket_of(src[3 * tid])], 1);
        __syncthreads();
        g_seghist[ab][sg][tid] = sint[tid];
        if (bid == 0 && tid == 0) { out[0] = 0.0f; g_nfail = 0; }
    }
    gbar(0);

    // ---------- P1: cross-segment scan (blocks 0..7 = ab) + bestbits init ----------
    if (bid < 8) {
        int* wsum = sint + 2048;
        const int ab = bid;
        const int a = ab >> 2, b = ab & 3;
        const int lane = tid & 31, warp = tid >> 5;

        int segc[8];
        int cnt = 0;
        #pragma unroll
        for (int sg = 0; sg < 8; sg++) {
            segc[sg] = g_seghist[ab][sg][tid];
            cnt += segc[sg];
        }
        int v = cnt;
        #pragma unroll
        for (int o = 1; o < 32; o <<= 1) {
            int u = __shfl_up_sync(0xffffffffu, v, o);
            if (lane >= o) v += u;
        }
        if (lane == 31) wsum[warp] = v;
        __syncthreads();
        if (tid < 32) {
            int w = wsum[tid];
            #pragma unroll
            for (int o = 1; o < 32; o <<= 1) {
                int u = __shfl_up_sync(0xffffffffu, w, o);
                if (tid >= o) w += u;
            }
            wsum[tid] = w;
        }
        __syncthreads();
        const int incl = v + (warp ? wsum[warp - 1] : 0);
        int base = incl - cnt;
        g_off[a][b][tid] = base;
        if (tid == NB - 1) g_off[a][b][NB] = incl;
        #pragma unroll
        for (int sg = 0; sg < 8; sg++) {
            g_segbase[ab][sg][tid] = base;
            base += segc[sg];
        }
        unsigned* bb = (unsigned*)g_bestbits;
        #pragma unroll
        for (int k = 0; k < 8; k++)
            bb[ab * 1024 + tid + k * 8192] = 0x7f800000u;
    }
    gbar(1);

    // ---------- P2: scatter ----------
    if (bid < 64) {
        const int ab = bid >> 3, sg = bid & 7;
        const int a = ab >> 2, b = ab & 3;
        const float* __restrict__ src = (a ? p2 : p1) + (b * NPTS + sg * 1024) * 3;
        sint[tid] = g_segbase[ab][sg][tid];
        __syncthreads();
        float x = src[3 * tid], y = src[3 * tid + 1], z = src[3 * tid + 2];
        float w = fmaf(x, x, fmaf(y, y, z * z));
        int pos = atomicAdd(&sint[bucket_of(x)], 1);
        g_sorted[a][b * NPTS + pos] = make_float4(x, y, z, w);
    }
    gbar(2);

    // ---------- P3: nn — 1024 subunits of 128 threads (8 per block) ----------
    {
        const int s = tid >> 7, lt = tid & 127;
        const int uid = bid * 8 + s;
        if (uid < 1024) {
            const int dir = uid >> 9;
            const int r   = uid & 511;
            const int b   = r >> 7;
            const int r2  = r & 127;
            const int qc  = r2 >> 2;
            const int w   = r2 & 3;
            const int qbase = qc * QB;

            const float4* __restrict__ qs   = &g_sorted[dir][b * NPTS] + qbase;
            const float4* __restrict__ cand = &g_sorted[dir ^ 1][b * NPTS];
            const int*    __restrict__ off  = g_off[dir ^ 1][b];

            int c0 = off[bucket_of(qs[QB / 2].x)] - CWIN / 2;   // per-thread, identical
            c0 = max(0, min(c0, NPTS - CWIN));
            const int base = c0 + w * QWIN;

            float4* sc = smem4 + s * QWIN;
            #pragma unroll
            for (int j = lt; j < QWIN; j += 128)
                sc[j] = cand[base + j];
            asm volatile("bar.sync %0, %1;" :: "r"(s + 1), "r"(128) : "memory");

            const float4 q0 = qs[lt];
            const float4 q1 = qs[lt + 128];
            const float ax = -2.0f * q0.x, ay = -2.0f * q0.y, az = -2.0f * q0.z;
            const float bx = -2.0f * q1.x, by = -2.0f * q1.y, bz = -2.0f * q1.z;

            float m0 = 3.4e38f, m1 = 3.4e38f;     // (cn - 2 q.c); +qn deferred
            #pragma unroll 1
            for (int m = 0; m < QWIN; m += 8) {
                float4 cbuf[8];
                #pragma unroll
                for (int j = 0; j < 8; j++)
                    cbuf[j] = sc[m + j];
                #pragma unroll
                for (int j = 0; j < 8; j++) {
                    const float4 c = cbuf[j];
                    float t0 = fmaf(az, c.z, c.w);
                    float t1 = fmaf(bz, c.z, c.w);
                    t0 = fmaf(ay, c.y, t0);
                    t1 = fmaf(by, c.y, t1);
                    t0 = fmaf(ax, c.x, t0);
                    t1 = fmaf(bx, c.x, t1);
                    m0 = fminf(m0, t0);
                    m1 = fminf(m1, t1);
                }
            }
            const float d0 = fmaxf(m0 + q0.w, 0.0f);   // clamp for uint ordering
            const float d1 = fmaxf(m1 + q1.w, 0.0f);

            unsigned* bb = &g_bestbits[dir][b * NPTS + qbase];
            atomicMin(&bb[lt], __float_as_uint(d0));
            atomicMin(&bb[lt + 128], __float_as_uint(d1));
        }
    }
    gbar(3);

    // ---------- P4: certify — 256 subunits of 256 threads ----------
    {
        const int su = tid >> 8, ct = tid & 255;
        const int cid = bid * 4 + su;
        if (cid < 256) {
            const int dir = cid >> 7;
            const int r   = cid & 127;
            const int b   = r >> 5;
            const int qc  = r & 31;
            const int qbase = qc * QB;

            const float4* __restrict__ qs   = &g_sorted[dir][b * NPTS] + qbase;
            const float4* __restrict__ cand = &g_sorted[dir ^ 1][b * NPTS];
            const int*    __restrict__ off  = g_off[dir ^ 1][b];

            int c0 = off[bucket_of(qs[QB / 2].x)] - CWIN / 2;   // per-thread, identical
            c0 = max(0, min(c0, NPTS - CWIN));
            const float el = XMIN + (float)(bucket_of(cand[c0].x) + 1) * BH;
            const float er = XMIN + (float)bucket_of(cand[c0 + CWIN - 1].x) * BH;
            const bool lok = (c0 == 0);
            const bool rok = (c0 + CWIN >= NPTS);

            const float qx = qs[ct].x;
            const float d = __uint_as_float(g_bestbits[dir][b * NPTS + qbase + ct]);

            const bool safe = (lok || (qx >= el && (qx - el) * (qx - el) >= d)) &&
                              (rok || (qx <= er && (er - qx) * (er - qx) >= d));

            // warp-aggregated fail push
            const unsigned mask = __ballot_sync(0xffffffffu, !safe);
            const int lane = ct & 31;
            if (mask) {
                int fbase = 0;
                if (lane == 0) fbase = atomicAdd(&g_nfail, __popc(mask));
                fbase = __shfl_sync(0xffffffffu, fbase, 0);
                if (!safe) {
                    int rk = __popc(mask & ((1u << lane) - 1u));
                    g_fail[fbase + rk] = dir * TOTAL + b * NPTS + qbase + ct;
                }
            }

            float contrib = safe ? d : 0.0f;
            #pragma unroll
            for (int o = 16; o; o >>= 1)
                contrib += __shfl_down_sync(0xffffffffu, contrib, o);
            if (lane == 0 && contrib != 0.0f) atomicAdd(out, contrib * SCALE);
        }
    }
    gbar(4);

    // ---------- P5: fallback — all warps grid-stride the fail list ----------
    {
        const int gw = (bid * 1024 + tid) >> 5;
        const int lane = tid & 31;
        const int nf = g_nfail;

        float acc = 0.0f;
        for (int f = gw; f < nf; f += GRID * 32) {
            const int g = g_fail[f];
            const int dir = g / TOTAL;
            const int rem = g - dir * TOTAL;
            const int b = rem / NPTS;

            const float4 q = g_sorted[dir][rem];
            const float bestd = __uint_as_float(g_bestbits[dir][rem]);
            const float4* __restrict__ cand = &g_sorted[dir ^ 1][b * NPTS];
            const int* __restrict__ off = g_off[dir ^ 1][b];

            const float s = sqrtf(bestd);
            const int lo = off[bucket_of(q.x - s)];
            const int hi = off[bucket_of(q.x + s) + 1];

            const float ax = -2.0f * q.x, ay = -2.0f * q.y, az = -2.0f * q.z;
            float best = bestd - q.w;
            for (int i = lo + lane; i < hi; i += 32) {
                float4 c = cand[i];
                float t = fmaf(az, c.z, c.w);
                t = fmaf(ay, c.y, t);
                t = fmaf(ax, c.x, t);
                best = fminf(best, t);
            }
            #pragma unroll
            for (int o = 16; o; o >>= 1)
                best = fminf(best, __shfl_xor_sync(0xffffffffu, best, o));
            if (lane == 0) acc += best + q.w;
        }
        if (acc != 0.0f) atomicAdd(out, acc * SCALE);
    }
}

extern "C" void kernel_launch(void* const* d_in, const int* in_sizes, int n_in,
                              void* d_out, int out_size) {
    const float* p1 = (const float*)d_in[0];
    const float* p2 = (const float*)d_in[1];
    float* out = (float*)d_out;

    mega_kernel<<<GRID, 1024>>>(p1, p2, out);
}

// round 17
// speedup vs baseline: 1.0007x; 1.0007x over previous
#include <cuda_runtime.h>

#define BATCH  4
#define NPTS   8192
#define TOTAL  (BATCH * NPTS)
#define NB     1024
#define NSEG   16            // segments per (array,batch), 512 pts each
#define SEGPTS 512
#define XMIN   (-5.0f)
#define BH     (10.0f / (float)NB)
#define INVH   ((float)NB / 10.0f)

#define QB    256            // queries per tile
#define CWIN  1280           // full certification window
#define QWIN  (CWIN / 4)     // 320 candidates per nn subunit
#define GRID  148            // persistent blocks (1 per SM, co-resident)

#define SCALE (1.0f / (float)TOTAL)

// Scratch (__device__ globals — no allocation allowed):
__device__ float4   g_sorted[2][TOTAL];       // (x,y,z,|p|^2), bucket-sorted by x
__device__ int      g_seghist[8][NSEG][NB];
__device__ int      g_segbase[8][NSEG][NB];
__device__ int      g_off[2][BATCH][NB + 1];
__device__ unsigned g_bestbits[2][TOTAL];     // merged window min (float bits, >=0)
__device__ int      g_nfail;
__device__ int      g_fail[2 * TOTAL];
__device__ unsigned g_bcnt[8];                // barrier counters (self-reset)
__device__ unsigned g_bgen[8];                // barrier generations (monotone)

__device__ __forceinline__ int bucket_of(float x) {
    int b = (int)floorf((x - XMIN) * INVH);
    return min(max(b, 0), NB - 1);
}

// Device-wide barrier: all GRID blocks co-resident (1 block/SM).
__device__ __forceinline__ void gbar(int i) {
    __syncthreads();
    if (threadIdx.x == 0) {
        volatile unsigned* genp = &g_bgen[i];
        unsigned g = *genp;
        __threadfence();
        if (atomicAdd(&g_bcnt[i], 1u) == GRID - 1u) {
            g_bcnt[i] = 0u;          // reset for next graph replay
            __threadfence();
            atomicAdd(&g_bgen[i], 1u);
        } else {
            while (*genp == g) __nanosleep(64);
        }
    }
    __syncthreads();
}

__global__ __launch_bounds__(1024, 1) void mega_kernel(const float* __restrict__ p1,
                                                       const float* __restrict__ p2,
                                                       float* __restrict__ out) {
    __shared__ float4 smem4[7 * QWIN];        // 35 KB, re-aliased per phase
    int* sint = (int*)smem4;

    const int tid = threadIdx.x;
    const int bid = blockIdx.x;

    // ---------- P0: per-segment histogram (128 segments = 8 ab x 16 seg) ----------
    if (bid < 128) {
        const int ab = bid >> 4, sg = bid & 15;
        const int a = ab >> 2, b = ab & 3;
        const float* __restrict__ src = (a ? p2 : p1) + (b * NPTS + sg * SEGPTS) * 3;
        sint[tid] = 0;
        __syncthreads();
        if (tid < SEGPTS) atomicAdd(&sint[bucket_of(src[3 * tid])], 1);
        __syncthreads();
        g_seghist[ab][sg][tid] = sint[tid];
        if (bid == 0 && tid == 0) { out[0] = 0.0f; g_nfail = 0; }
    }
    gbar(0);

    // ---------- P1: cross-segment scan (blocks 0..7 = ab) + bestbits init ----------
    if (bid < 8) {
        int* wsum = sint + 1024;
        const int ab = bid;
        const int a = ab >> 2, b = ab & 3;
        const int lane = tid & 31, warp = tid >> 5;

        int segc[NSEG];
        int cnt = 0;
        #pragma unroll
        for (int sg = 0; sg < NSEG; sg++) {
            segc[sg] = g_seghist[ab][sg][tid];
            cnt += segc[sg];
        }
        int v = cnt;
        #pragma unroll
        for (int o = 1; o < 32; o <<= 1) {
            int u = __shfl_up_sync(0xffffffffu, v, o);
            if (lane >= o) v += u;
        }
        if (lane == 31) wsum[warp] = v;
        __syncthreads();
        if (tid < 32) {
            int w = wsum[tid];
            #pragma unroll
            for (int o = 1; o < 32; o <<= 1) {
                int u = __shfl_up_sync(0xffffffffu, w, o);
                if (tid >= o) w += u;
            }
            wsum[tid] = w;
        }
        __syncthreads();
        const int incl = v + (warp ? wsum[warp - 1] : 0);
        int base = incl - cnt;
        g_off[a][b][tid] = base;
        if (tid == NB - 1) g_off[a][b][NB] = incl;
        #pragma unroll
        for (int sg = 0; sg < NSEG; sg++) {
            g_segbase[ab][sg][tid] = base;
            base += segc[sg];
        }
        unsigned* bb = (unsigned*)g_bestbits;
        #pragma unroll
        for (int k = 0; k < 8; k++)
            bb[ab * 1024 + tid + k * 8192] = 0x7f800000u;
    }
    gbar(1);

    // ---------- P2: scatter ----------
    if (bid < 128) {
        const int ab = bid >> 4, sg = bid & 15;
        const int a = ab >> 2, b = ab & 3;
        const float* __restrict__ src = (a ? p2 : p1) + (b * NPTS + sg * SEGPTS) * 3;
        sint[tid] = g_segbase[ab][sg][tid];
        __syncthreads();
        if (tid < SEGPTS) {
            float x = src[3 * tid], y = src[3 * tid + 1], z = src[3 * tid + 2];
            float w = fmaf(x, x, fmaf(y, y, z * z));
            int pos = atomicAdd(&sint[bucket_of(x)], 1);
            g_sorted[a][b * NPTS + pos] = make_float4(x, y, z, w);
        }
    }
    gbar(2);

    // ---------- P3: nn — 1024 subunits of 128 threads, balanced over 148 blocks ----------
    {
        const int s = tid >> 7, lt = tid & 127;
        const int uid = s * GRID + bid;       // s=0..6 cover 1036 slots
        if (s < 7 && uid < 1024) {
            const int dir = uid >> 9;
            const int r   = uid & 511;
            const int b   = r >> 7;
            const int r2  = r & 127;
            const int qc  = r2 >> 2;
            const int w   = r2 & 3;
            const int qbase = qc * QB;

            const float4* __restrict__ qs   = &g_sorted[dir][b * NPTS] + qbase;
            const float4* __restrict__ cand = &g_sorted[dir ^ 1][b * NPTS];
            const int*    __restrict__ off  = g_off[dir ^ 1][b];

            int c0 = off[bucket_of(qs[QB / 2].x)] - CWIN / 2;   // per-thread, identical
            c0 = max(0, min(c0, NPTS - CWIN));
            const int base = c0 + w * QWIN;

            float4* sc = smem4 + s * QWIN;
            #pragma unroll
            for (int j = lt; j < QWIN; j += 128)
                sc[j] = cand[base + j];
            asm volatile("bar.sync %0, %1;" :: "r"(s + 1), "r"(128) : "memory");

            const float4 q0 = qs[lt];
            const float4 q1 = qs[lt + 128];
            const float ax = -2.0f * q0.x, ay = -2.0f * q0.y, az = -2.0f * q0.z;
            const float bx = -2.0f * q1.x, by = -2.0f * q1.y, bz = -2.0f * q1.z;

            float m0 = 3.4e38f, m1 = 3.4e38f;     // (cn - 2 q.c); +qn deferred
            #pragma unroll 1
            for (int m = 0; m < QWIN; m += 8) {
                float4 cbuf[8];
                #pragma unroll
                for (int j = 0; j < 8; j++)
                    cbuf[j] = sc[m + j];
                #pragma unroll
                for (int j = 0; j < 8; j++) {
                    const float4 c = cbuf[j];
                    float t0 = fmaf(az, c.z, c.w);
                    float t1 = fmaf(bz, c.z, c.w);
                    t0 = fmaf(ay, c.y, t0);
                    t1 = fmaf(by, c.y, t1);
                    t0 = fmaf(ax, c.x, t0);
                    t1 = fmaf(bx, c.x, t1);
                    m0 = fminf(m0, t0);
                    m1 = fminf(m1, t1);
                }
            }
            const float d0 = fmaxf(m0 + q0.w, 0.0f);   // clamp for uint ordering
            const float d1 = fmaxf(m1 + q1.w, 0.0f);

            unsigned* bb = &g_bestbits[dir][b * NPTS + qbase];
            atomicMin(&bb[lt], __float_as_uint(d0));
            atomicMin(&bb[lt + 128], __float_as_uint(d1));
        }
    }
    gbar(3);

    // ---------- P4: certify — 256 subunits of 256 threads, balanced ----------
    {
        const int su = tid >> 8, ct = tid & 255;
        const int cid = su * GRID + bid;      // su=0..1 cover 296 slots
        if (su < 2 && cid < 256) {
            const int dir = cid >> 7;
            const int r   = cid & 127;
            const int b   = r >> 5;
            const int qc  = r & 31;
            const int qbase = qc * QB;

            const float4* __restrict__ qs   = &g_sorted[dir][b * NPTS] + qbase;
            const float4* __restrict__ cand = &g_sorted[dir ^ 1][b * NPTS];
            const int*    __restrict__ off  = g_off[dir ^ 1][b];

            int c0 = off[bucket_of(qs[QB / 2].x)] - CWIN / 2;   // per-thread, identical
            c0 = max(0, min(c0, NPTS - CWIN));
            const float el = XMIN + (float)(bucket_of(cand[c0].x) + 1) * BH;
            const float er = XMIN + (float)bucket_of(cand[c0 + CWIN - 1].x) * BH;
            const bool lok = (c0 == 0);
            const bool rok = (c0 + CWIN >= NPTS);

            const float qx = qs[ct].x;
            const float d = __uint_as_float(g_bestbits[dir][b * NPTS + qbase + ct]);

            const bool safe = (lok || (qx >= el && (qx - el) * (qx - el) >= d)) &&
                              (rok || (qx <= er && (er - qx) * (er - qx) >= d));

            // warp-aggregated fail push
            const unsigned mask = __ballot_sync(0xffffffffu, !safe);
            const int lane = ct & 31;
            if (mask) {
                int fbase = 0;
                if (lane == 0) fbase = atomicAdd(&g_nfail, __popc(mask));
                fbase = __shfl_sync(0xffffffffu, fbase, 0);
                if (!safe) {
                    int rk = __popc(mask & ((1u << lane) - 1u));
                    g_fail[fbase + rk] = dir * TOTAL + b * NPTS + qbase + ct;
                }
            }

            float contrib = safe ? d : 0.0f;
            #pragma unroll
            for (int o = 16; o; o >>= 1)
                contrib += __shfl_down_sync(0xffffffffu, contrib, o);
            if (lane == 0 && contrib != 0.0f) atomicAdd(out, contrib * SCALE);
        }
    }
    gbar(4);

    // ---------- P5: fallback — all warps grid-stride the fail list ----------
    {
        const int gw = (bid * 1024 + tid) >> 5;
        const int lane = tid & 31;
        const int nf = g_nfail;

        float acc = 0.0f;
        for (int f = gw; f < nf; f += GRID * 32) {
            const int g = g_fail[f];
            const int dir = g / TOTAL;
            const int rem = g - dir * TOTAL;
            const int b = rem / NPTS;

            const float4 q = g_sorted[dir][rem];
            const float bestd = __uint_as_float(g_bestbits[dir][rem]);
            const float4* __restrict__ cand = &g_sorted[dir ^ 1][b * NPTS];
            const int* __restrict__ off = g_off[dir ^ 1][b];

            const float s = sqrtf(bestd);
            const int lo = off[bucket_of(q.x - s)];
            const int hi = off[bucket_of(q.x + s) + 1];

            const float ax = -2.0f * q.x, ay = -2.0f * q.y, az = -2.0f * q.z;
            float best = bestd - q.w;
            for (int i = lo + lane; i < hi; i += 32) {
                float4 c = cand[i];
                float t = fmaf(az, c.z, c.w);
                t = fmaf(ay, c.y, t);
                t = fmaf(ax, c.x, t);
                best = fminf(best, t);
            }
            #pragma unroll
            for (int o = 16; o; o >>= 1)
                best = fminf(best, __shfl_xor_sync(0xffffffffu, best, o));
            if (lane == 0) acc += best + q.w;
        }
        if (acc != 0.0f) atomicAdd(out, acc * SCALE);
    }
}

extern "C" void kernel_launch(void* const* d_in, const int* in_sizes, int n_in,
                              void* d_out, int out_size) {
    const float* p1 = (const float*)d_in[0];
    const float* p2 = (const float*)d_in[1];
    float* out = (float*)d_out;

    mega_kernel<<<GRID, 1024>>>(p1, p2, out);
}